// round 5
// baseline (speedup 1.0000x reference)
#include <cuda_runtime.h>
#include <cstdint>

#define NN 100000
#define NE 1600000
#define HD 64
#define IND 5
#define OUTD 4
#define BN_EPS 1e-5f
#define TS 65   // padded tile row stride (floats)

// ---------------- scratch (static; no allocation allowed) ----------------
__device__ float  g_xw[(size_t)NN * HD];
__device__ float  g_agg[(size_t)NN * HD];
__device__ int    g_cnt_s[NN], g_cnt_t[NN];
__device__ int    g_start_s[NN], g_start_t[NN];
__device__ int    g_cur_s[NN],  g_cur_t[NN];
__device__ float  g_dv_s[NN],  g_dv_t[NN];
__device__ int2   g_adj_s[NE], g_adj_t[NE];      // (row, norm-bits), grouped by col
__device__ double g_sum[HD], g_sumsq[HD];
__device__ float  g_a[HD], g_c[HD];              // BN scale/shift

static inline int cdiv(long long a, int b) { return (int)((a + b - 1) / b); }

// ---------------- CSR build ----------------
__global__ void zero_cnt_kernel(int* a, int* b, int n) {
    int i = blockIdx.x * blockDim.x + threadIdx.x;
    if (i < n) { a[i] = 0; b[i] = 0; }
}

// both graphs in one pass
__global__ void count_kernel(const int* __restrict__ s_cols, const int* __restrict__ t_cols,
                             int* __restrict__ cnt_s, int* __restrict__ cnt_t, int nE) {
    int e = blockIdx.x * blockDim.x + threadIdx.x;
    if (e < nE) {
        atomicAdd(&cnt_s[s_cols[e]], 1);
        atomicAdd(&cnt_t[t_cols[e]], 1);
    }
}

__global__ void dinv_kernel(const int* __restrict__ ca, const int* __restrict__ cb,
                            float* __restrict__ da, float* __restrict__ db, int n) {
    int i = blockIdx.x * blockDim.x + threadIdx.x;
    if (i < n) {
        da[i] = rsqrtf((float)ca[i] + 1.0f);
        db[i] = rsqrtf((float)cb[i] + 1.0f);
    }
}

// grid = 2 blocks (one per graph), 1024 threads. Exclusive scan of counts.
__global__ void scan_kernel(const int* __restrict__ cnt_s, int* __restrict__ start_s, int* __restrict__ cur_s,
                            const int* __restrict__ cnt_t, int* __restrict__ start_t, int* __restrict__ cur_t,
                            int n) {
    const int* cnt = blockIdx.x ? cnt_t : cnt_s;
    int* start = blockIdx.x ? start_t : start_s;
    int* cur   = blockIdx.x ? cur_t   : cur_s;
    int t = threadIdx.x;
    int chunk = (n + 1023) / 1024;
    int lo = t * chunk, hi = min(lo + chunk, n);
    int s = 0;
    for (int i = lo; i < hi; i++) s += cnt[i];
    __shared__ int sh[1024];
    sh[t] = s;
    __syncthreads();
    for (int off = 1; off < 1024; off <<= 1) {
        int v = (t >= off) ? sh[t - off] : 0;
        __syncthreads();
        sh[t] += v;
        __syncthreads();
    }
    int run = (t == 0) ? 0 : sh[t - 1];
    for (int i = lo; i < hi; i++) {
        start[i] = run; cur[i] = run;
        run += cnt[i];
    }
}

// both graphs in one pass
__global__ void place_kernel(const int* __restrict__ s_rows, const int* __restrict__ s_cols,
                             const int* __restrict__ t_rows, const int* __restrict__ t_cols,
                             const float* __restrict__ dv_s, const float* __restrict__ dv_t,
                             int* __restrict__ cur_s, int* __restrict__ cur_t,
                             int2* __restrict__ adj_s, int2* __restrict__ adj_t, int nE) {
    int e = blockIdx.x * blockDim.x + threadIdx.x;
    if (e >= nE) return;
    {
        int r = s_rows[e], c = s_cols[e];
        int pos = atomicAdd(&cur_s[c], 1);
        adj_s[pos] = make_int2(r, __float_as_int(dv_s[r] * dv_s[c]));
    }
    {
        int r = t_rows[e], c = t_cols[e];
        int pos = atomicAdd(&cur_t[c], 1);
        adj_t[pos] = make_int2(r, __float_as_int(dv_t[r] * dv_t[c]));
    }
}

// ---------------- layer 1 projection: xw = x(Nx5) @ w1(5x64) ----------------
__global__ void xw1_kernel(const float* __restrict__ x, const float* __restrict__ w,
                           float* __restrict__ out, int n) {
    __shared__ float Ws[IND * HD];
    int t = threadIdx.x;
    if (blockIdx.x == 0 && t < HD) { g_sum[t] = 0.0; g_sumsq[t] = 0.0; }
    for (int i = t; i < IND * HD; i += blockDim.x) Ws[i] = w[i];
    __syncthreads();
    int idx = blockIdx.x * blockDim.x + t;
    int node = idx >> 4, q = idx & 15;
    if (node >= n) return;
    float xr[IND];
    #pragma unroll
    for (int k = 0; k < IND; k++) xr[k] = __ldg(&x[(size_t)node * IND + k]);
    float4 a = make_float4(0.f, 0.f, 0.f, 0.f);
    #pragma unroll
    for (int k = 0; k < IND; k++) {
        const float* wr = &Ws[k * HD + q * 4];
        a.x = fmaf(xr[k], wr[0], a.x);
        a.y = fmaf(xr[k], wr[1], a.y);
        a.z = fmaf(xr[k], wr[2], a.z);
        a.w = fmaf(xr[k], wr[3], a.w);
    }
    ((float4*)out)[(size_t)node * 16 + q] = a;
}

// ---------------- aggregation (gather over CSR) + fused BN stats ----------------
// agg[c] = b + dinv[c]^2 * xw[c] + sum_{edges into c} norm * xw[row]
// 16 lanes per node; unroll-4 batched loads for MLP; BN stats fused.
__global__ void __launch_bounds__(256)
gather_kernel(const int2* __restrict__ adj, const int* __restrict__ start,
              const int* __restrict__ cnt, const float* __restrict__ dinv,
              const float* __restrict__ xw, const float* __restrict__ bias,
              float* __restrict__ agg, int n) {
    __shared__ float sh_sum[HD], sh_sq[HD];
    int t = threadIdx.x;
    if (t < HD) { sh_sum[t] = 0.f; sh_sq[t] = 0.f; }
    __syncthreads();

    int idx = blockIdx.x * 256 + t;
    int node = idx >> 4, q = idx & 15;
    float4 acc = make_float4(0.f, 0.f, 0.f, 0.f);

    if (node < n) {
        const float4* xw4 = (const float4*)xw;
        acc = __ldg(&((const float4*)bias)[q]);
        float s = dinv[node]; s *= s;
        float4 self = __ldg(&xw4[(size_t)node * 16 + q]);
        acc.x = fmaf(s, self.x, acc.x);
        acc.y = fmaf(s, self.y, acc.y);
        acc.z = fmaf(s, self.z, acc.z);
        acc.w = fmaf(s, self.w, acc.w);

        int p  = start[node];
        int p1 = p + cnt[node];
        // unroll-4: batch all loads before FMAs to maximize loads in flight
        for (; p + 4 <= p1; p += 4) {
            int2 a0 = __ldg(&adj[p]);
            int2 a1 = __ldg(&adj[p + 1]);
            int2 a2 = __ldg(&adj[p + 2]);
            int2 a3 = __ldg(&adj[p + 3]);
            float4 v0 = __ldg(&xw4[(size_t)a0.x * 16 + q]);
            float4 v1 = __ldg(&xw4[(size_t)a1.x * 16 + q]);
            float4 v2 = __ldg(&xw4[(size_t)a2.x * 16 + q]);
            float4 v3 = __ldg(&xw4[(size_t)a3.x * 16 + q]);
            float w0 = __int_as_float(a0.y), w1 = __int_as_float(a1.y);
            float w2 = __int_as_float(a2.y), w3 = __int_as_float(a3.y);
            acc.x = fmaf(w3, v3.x, fmaf(w2, v2.x, fmaf(w1, v1.x, fmaf(w0, v0.x, acc.x))));
            acc.y = fmaf(w3, v3.y, fmaf(w2, v2.y, fmaf(w1, v1.y, fmaf(w0, v0.y, acc.y))));
            acc.z = fmaf(w3, v3.z, fmaf(w2, v2.z, fmaf(w1, v1.z, fmaf(w0, v0.z, acc.z))));
            acc.w = fmaf(w3, v3.w, fmaf(w2, v2.w, fmaf(w1, v1.w, fmaf(w0, v0.w, acc.w))));
        }
        for (; p < p1; p++) {
            int2 a = __ldg(&adj[p]);
            float w = __int_as_float(a.y);
            float4 v = __ldg(&xw4[(size_t)a.x * 16 + q]);
            acc.x = fmaf(w, v.x, acc.x);
            acc.y = fmaf(w, v.y, acc.y);
            acc.z = fmaf(w, v.z, acc.z);
            acc.w = fmaf(w, v.w, acc.w);
        }
        ((float4*)agg)[(size_t)node * 16 + q] = acc;
    }

    // fused BN stats (all threads participate; inactive threads contribute 0)
    int c0 = q * 4;
    atomicAdd(&sh_sum[c0 + 0], acc.x);
    atomicAdd(&sh_sum[c0 + 1], acc.y);
    atomicAdd(&sh_sum[c0 + 2], acc.z);
    atomicAdd(&sh_sum[c0 + 3], acc.w);
    atomicAdd(&sh_sq[c0 + 0], acc.x * acc.x);
    atomicAdd(&sh_sq[c0 + 1], acc.y * acc.y);
    atomicAdd(&sh_sq[c0 + 2], acc.z * acc.z);
    atomicAdd(&sh_sq[c0 + 3], acc.w * acc.w);
    __syncthreads();
    if (t < HD) {
        atomicAdd(&g_sum[t], (double)sh_sum[t]);
        atomicAdd(&g_sumsq[t], (double)sh_sq[t]);
    }
}

__global__ void bn_finalize_kernel(const float* __restrict__ g, const float* __restrict__ be, int n) {
    int t = threadIdx.x;
    if (t >= HD) return;
    double mean = g_sum[t] / n;
    double var  = g_sumsq[t] / n - mean * mean;
    float a = g[t] * rsqrtf((float)var + BN_EPS);
    g_a[t] = a;
    g_c[t] = be[t] - (float)mean * a;
}

// ---------------- fused BN+ReLU+GEMM: xw = relu(bn(agg)) @ W ----------------
// block = 128 threads = 64 nodes, 2 threads per node (32 outputs each).
// Block 0 also zeroes BN stat accumulators for the following gather.
__global__ void __launch_bounds__(128)
xw_fused_kernel(const float* __restrict__ in, const float* __restrict__ W,
                float* __restrict__ out, int n) {
    __shared__ float tile[64 * TS];
    __shared__ float Ws[HD * HD];
    __shared__ float as[HD], cs[HD];
    int t = threadIdx.x;
    if (blockIdx.x == 0 && t < HD) { g_sum[t] = 0.0; g_sumsq[t] = 0.0; }
    for (int i = t; i < HD * HD; i += 128) Ws[i] = W[i];
    if (t < HD) { as[t] = g_a[t]; cs[t] = g_c[t]; }

    int base = blockIdx.x * 64;
    int nv = min(64, n - base);
    const float4* in4 = (const float4*)(in + (size_t)base * HD);
    for (int i = t; i < nv * 16; i += 128) {
        float4 v = __ldg(&in4[i]);
        float* p = &tile[(i >> 4) * TS + (i & 15) * 4];
        p[0] = v.x; p[1] = v.y; p[2] = v.z; p[3] = v.w;
    }
    __syncthreads();

    int node = t >> 1, h = t & 1;
    bool act = (base + node) < n;
    float acc[32];
    #pragma unroll
    for (int j = 0; j < 32; j++) acc[j] = 0.f;
    if (act) {
        const float* row = &tile[node * TS];
        const float* wb  = &Ws[h * 32];
        #pragma unroll 4
        for (int k = 0; k < HD; k++) {
            float v = fmaxf(fmaf(row[k], as[k], cs[k]), 0.f);
            #pragma unroll
            for (int j = 0; j < 32; j++) acc[j] = fmaf(v, wb[k * HD + j], acc[j]);
        }
    }
    __syncthreads();
    if (act) {
        float* dst = &tile[node * TS + h * 32];
        #pragma unroll
        for (int j = 0; j < 32; j++) dst[j] = acc[j];
    }
    __syncthreads();
    float4* out4 = (float4*)(out + (size_t)base * HD);
    for (int i = t; i < nv * 16; i += 128) {
        float* p = &tile[(i >> 4) * TS + (i & 15) * 4];
        out4[i] = make_float4(p[0], p[1], p[2], p[3]);
    }
}

// ---------------- final FC: out = relu(bn(agg)) @ wfc + bfc ----------------
__global__ void __launch_bounds__(128)
fc_kernel(const float* __restrict__ agg, const float* __restrict__ wfc,
          const float* __restrict__ bfc, float* __restrict__ out, int n) {
    __shared__ float tile[128 * TS];
    __shared__ float Wf[HD * OUTD];
    __shared__ float as[HD], cs[HD];
    int t = threadIdx.x;
    if (t < HD) { as[t] = g_a[t]; cs[t] = g_c[t]; }
    if (t < HD) ((float4*)Wf)[t] = ((const float4*)wfc)[t];

    int base = blockIdx.x * 128;
    int nv = min(128, n - base);
    const float4* in4 = (const float4*)(agg + (size_t)base * HD);
    for (int i = t; i < nv * 16; i += 128) {
        float4 v = __ldg(&in4[i]);
        float* p = &tile[(i >> 4) * TS + (i & 15) * 4];
        p[0] = v.x; p[1] = v.y; p[2] = v.z; p[3] = v.w;
    }
    __syncthreads();
    if (t < nv) {
        float a0 = __ldg(&bfc[0]), a1 = __ldg(&bfc[1]);
        float a2 = __ldg(&bfc[2]), a3 = __ldg(&bfc[3]);
        const float* row = &tile[t * TS];
        #pragma unroll 8
        for (int k = 0; k < HD; k++) {
            float v = fmaxf(fmaf(row[k], as[k], cs[k]), 0.f);
            a0 = fmaf(v, Wf[k * 4 + 0], a0);
            a1 = fmaf(v, Wf[k * 4 + 1], a1);
            a2 = fmaf(v, Wf[k * 4 + 2], a2);
            a3 = fmaf(v, Wf[k * 4 + 3], a3);
        }
        ((float4*)out)[base + t] = make_float4(a0, a1, a2, a3);
    }
}

// ---------------- host orchestration ----------------
extern "C" void kernel_launch(void* const* d_in, const int* in_sizes, int n_in,
                              void* d_out, int out_size) {
    const float* x   = (const float*)d_in[0];
    const int*   sei = (const int*)d_in[1];
    const int*   tei = (const int*)d_in[2];
    const float* w1  = (const float*)d_in[3];
    const float* b1  = (const float*)d_in[4];
    const float* g1  = (const float*)d_in[5];
    const float* be1 = (const float*)d_in[6];
    const float* w2  = (const float*)d_in[7];
    const float* b2  = (const float*)d_in[8];
    const float* g2  = (const float*)d_in[9];
    const float* be2 = (const float*)d_in[10];
    const float* w3  = (const float*)d_in[11];
    const float* b3  = (const float*)d_in[12];
    const float* g3  = (const float*)d_in[13];
    const float* be3 = (const float*)d_in[14];
    const float* w4  = (const float*)d_in[15];
    const float* b4  = (const float*)d_in[16];
    const float* g4  = (const float*)d_in[17];
    const float* be4 = (const float*)d_in[18];
    const float* wfc = (const float*)d_in[19];
    const float* bfc = (const float*)d_in[20];
    float* out = (float*)d_out;

    const int n = in_sizes[0] / IND;   // 100000
    const int e = in_sizes[1] / 2;     // 1600000
    const int* s_rows = sei;  const int* s_cols = sei + e;
    const int* t_rows = tei;  const int* t_cols = tei + e;

    int *cnt_s, *cnt_t, *start_s, *start_t, *cur_s, *cur_t;
    float *dv_s, *dv_t, *xw, *agg;
    int2 *adj_s, *adj_t;
    cudaGetSymbolAddress((void**)&cnt_s, g_cnt_s);
    cudaGetSymbolAddress((void**)&cnt_t, g_cnt_t);
    cudaGetSymbolAddress((void**)&start_s, g_start_s);
    cudaGetSymbolAddress((void**)&start_t, g_start_t);
    cudaGetSymbolAddress((void**)&cur_s, g_cur_s);
    cudaGetSymbolAddress((void**)&cur_t, g_cur_t);
    cudaGetSymbolAddress((void**)&dv_s, g_dv_s);
    cudaGetSymbolAddress((void**)&dv_t, g_dv_t);
    cudaGetSymbolAddress((void**)&xw, g_xw);
    cudaGetSymbolAddress((void**)&agg, g_agg);
    cudaGetSymbolAddress((void**)&adj_s, g_adj_s);
    cudaGetSymbolAddress((void**)&adj_t, g_adj_t);

    const int eg = cdiv(e, 256);
    const int ng16 = cdiv((long long)n * 16, 256);

    // ---- CSR build (once per graph, reused by 2 layers each) ----
    zero_cnt_kernel<<<cdiv(n, 256), 256>>>(cnt_s, cnt_t, n);
    count_kernel<<<eg, 256>>>(s_cols, t_cols, cnt_s, cnt_t, e);
    dinv_kernel<<<cdiv(n, 256), 256>>>(cnt_s, cnt_t, dv_s, dv_t, n);
    scan_kernel<<<2, 1024>>>(cnt_s, start_s, cur_s, cnt_t, start_t, cur_t, n);
    place_kernel<<<eg, 256>>>(s_rows, s_cols, t_rows, t_cols, dv_s, dv_t,
                              cur_s, cur_t, adj_s, adj_t, e);

    // ---- layer 1 (spatial) ----
    xw1_kernel<<<ng16, 256>>>(x, w1, xw, n);
    gather_kernel<<<ng16, 256>>>(adj_s, start_s, cnt_s, dv_s, xw, b1, agg, n);
    bn_finalize_kernel<<<1, 64>>>(g1, be1, n);

    // ---- layer 2 (spatial) ----
    xw_fused_kernel<<<cdiv(n, 64), 128>>>(agg, w2, xw, n);
    gather_kernel<<<ng16, 256>>>(adj_s, start_s, cnt_s, dv_s, xw, b2, agg, n);
    bn_finalize_kernel<<<1, 64>>>(g2, be2, n);

    // ---- layer 3 (temporal) ----
    xw_fused_kernel<<<cdiv(n, 64), 128>>>(agg, w3, xw, n);
    gather_kernel<<<ng16, 256>>>(adj_t, start_t, cnt_t, dv_t, xw, b3, agg, n);
    bn_finalize_kernel<<<1, 64>>>(g3, be3, n);

    // ---- layer 4 (temporal) ----
    xw_fused_kernel<<<cdiv(n, 64), 128>>>(agg, w4, xw, n);
    gather_kernel<<<ng16, 256>>>(adj_t, start_t, cnt_t, dv_t, xw, b4, agg, n);
    bn_finalize_kernel<<<1, 64>>>(g4, be4, n);

    // ---- final FC ----
    fc_kernel<<<cdiv(n, 128), 128>>>(agg, wfc, bfc, out, n);
}

// round 7
// speedup vs baseline: 1.7859x; 1.7859x over previous
#include <cuda_runtime.h>
#include <cstdint>

#define NN 100000
#define NE 1600000
#define HD 64
#define IND 5
#define OUTD 4
#define BN_EPS 1e-5f
#define TS 65   // padded tile row stride (floats)
#define SCAN_NBLK 98   // cdiv(100000, 1024)

// ---------------- scratch (static; no allocation allowed) ----------------
__device__ float  g_xw[(size_t)NN * HD];
__device__ float  g_agg[(size_t)NN * HD];
__device__ int    g_cnt_s[NN], g_cnt_t[NN];
__device__ int    g_start_s[NN], g_start_t[NN];
__device__ int    g_cur_s[NN],  g_cur_t[NN];
__device__ float  g_dv_s[NN],  g_dv_t[NN];
__device__ int2   g_adj_s[NE], g_adj_t[NE];      // (row, norm-bits), grouped by col
__device__ int    g_bsum[256];                   // [2][128] block sums for scan
__device__ double g_sum[HD], g_sumsq[HD];
__device__ float  g_a[HD], g_c[HD];              // BN scale/shift

static inline int cdiv(long long a, int b) { return (int)((a + b - 1) / b); }

// ---------------- CSR build ----------------
__global__ void zero_cnt_kernel(int* a, int* b, int n) {
    int i = blockIdx.x * blockDim.x + threadIdx.x;
    if (i < n) { a[i] = 0; b[i] = 0; }
}

// both graphs in one pass
__global__ void count_kernel(const int* __restrict__ s_cols, const int* __restrict__ t_cols,
                             int* __restrict__ cnt_s, int* __restrict__ cnt_t, int nE) {
    int e = blockIdx.x * blockDim.x + threadIdx.x;
    if (e < nE) {
        atomicAdd(&cnt_s[s_cols[e]], 1);
        atomicAdd(&cnt_t[t_cols[e]], 1);
    }
}

__global__ void dinv_kernel(const int* __restrict__ ca, const int* __restrict__ cb,
                            float* __restrict__ da, float* __restrict__ db, int n) {
    int i = blockIdx.x * blockDim.x + threadIdx.x;
    if (i < n) {
        da[i] = rsqrtf((float)ca[i] + 1.0f);
        db[i] = rsqrtf((float)cb[i] + 1.0f);
    }
}

// ---- parallel 3-phase exclusive scan ----
// phase 1: per-block (1024-wide) scan; gridDim = (SCAN_NBLK, 2)
__global__ void scan1_kernel(const int* __restrict__ cnt_s, int* __restrict__ start_s,
                             const int* __restrict__ cnt_t, int* __restrict__ start_t,
                             int* __restrict__ bsum, int n) {
    const int* cnt = blockIdx.y ? cnt_t : cnt_s;
    int* start = blockIdx.y ? start_t : start_s;
    __shared__ int sh[1024];
    int t = threadIdx.x;
    int i = blockIdx.x * 1024 + t;
    int v = (i < n) ? cnt[i] : 0;
    sh[t] = v;
    __syncthreads();
    #pragma unroll
    for (int off = 1; off < 1024; off <<= 1) {
        int x = (t >= off) ? sh[t - off] : 0;
        __syncthreads();
        sh[t] += x;
        __syncthreads();
    }
    if (i < n) start[i] = sh[t] - v;   // exclusive within block
    if (t == 1023) bsum[blockIdx.y * 128 + blockIdx.x] = sh[1023];
}

// phase 2: exclusive scan of block sums; grid = 2 blocks of 128 threads
__global__ void scan2_kernel(int* __restrict__ bsum) {
    int* bs = bsum + blockIdx.x * 128;
    __shared__ int sh[128];
    int t = threadIdx.x;
    int v = (t < SCAN_NBLK) ? bs[t] : 0;
    sh[t] = v;
    __syncthreads();
    #pragma unroll
    for (int off = 1; off < 128; off <<= 1) {
        int x = (t >= off) ? sh[t - off] : 0;
        __syncthreads();
        sh[t] += x;
        __syncthreads();
    }
    bs[t] = sh[t] - v;   // exclusive
}

// phase 3: add block offsets; write start + cur; gridDim = (cdiv(n,256), 2)
__global__ void scan3_kernel(int* __restrict__ start_s, int* __restrict__ cur_s,
                             int* __restrict__ start_t, int* __restrict__ cur_t,
                             const int* __restrict__ bsum, int n) {
    int g = blockIdx.y;
    int* start = g ? start_t : start_s;
    int* cur   = g ? cur_t   : cur_s;
    int i = blockIdx.x * blockDim.x + threadIdx.x;
    if (i < n) {
        int v = start[i] + bsum[g * 128 + (i >> 10)];
        start[i] = v;
        cur[i] = v;
    }
}

// both graphs in one pass
__global__ void place_kernel(const int* __restrict__ s_rows, const int* __restrict__ s_cols,
                             const int* __restrict__ t_rows, const int* __restrict__ t_cols,
                             const float* __restrict__ dv_s, const float* __restrict__ dv_t,
                             int* __restrict__ cur_s, int* __restrict__ cur_t,
                             int2* __restrict__ adj_s, int2* __restrict__ adj_t, int nE) {
    int e = blockIdx.x * blockDim.x + threadIdx.x;
    if (e >= nE) return;
    {
        int r = s_rows[e], c = s_cols[e];
        int pos = atomicAdd(&cur_s[c], 1);
        adj_s[pos] = make_int2(r, __float_as_int(dv_s[r] * dv_s[c]));
    }
    {
        int r = t_rows[e], c = t_cols[e];
        int pos = atomicAdd(&cur_t[c], 1);
        adj_t[pos] = make_int2(r, __float_as_int(dv_t[r] * dv_t[c]));
    }
}

// ---------------- layer 1 projection: xw = x(Nx5) @ w1(5x64) ----------------
__global__ void xw1_kernel(const float* __restrict__ x, const float* __restrict__ w,
                           float* __restrict__ out, int n) {
    __shared__ float Ws[IND * HD];
    int t = threadIdx.x;
    for (int i = t; i < IND * HD; i += blockDim.x) Ws[i] = w[i];
    __syncthreads();
    int idx = blockIdx.x * blockDim.x + t;
    int node = idx >> 4, q = idx & 15;
    if (node >= n) return;
    float xr[IND];
    #pragma unroll
    for (int k = 0; k < IND; k++) xr[k] = __ldg(&x[(size_t)node * IND + k]);
    float4 a = make_float4(0.f, 0.f, 0.f, 0.f);
    #pragma unroll
    for (int k = 0; k < IND; k++) {
        const float* wr = &Ws[k * HD + q * 4];
        a.x = fmaf(xr[k], wr[0], a.x);
        a.y = fmaf(xr[k], wr[1], a.y);
        a.z = fmaf(xr[k], wr[2], a.z);
        a.w = fmaf(xr[k], wr[3], a.w);
    }
    ((float4*)out)[(size_t)node * 16 + q] = a;
}

// ---------------- aggregation (gather over CSR) ----------------
// agg[c] = b + dinv[c]^2 * xw[c] + sum_{edges into c} norm * xw[row]
// 16 lanes per node; unroll-4 batched loads for MLP. No trailing barrier.
// Block 0 zeroes the BN stat accumulators for the bn_stats that follows.
__global__ void __launch_bounds__(256)
gather_kernel(const int2* __restrict__ adj, const int* __restrict__ start,
              const int* __restrict__ cnt, const float* __restrict__ dinv,
              const float* __restrict__ xw, const float* __restrict__ bias,
              float* __restrict__ agg, int n) {
    int t = threadIdx.x;
    if (blockIdx.x == 0 && t < HD) { g_sum[t] = 0.0; g_sumsq[t] = 0.0; }
    int idx = blockIdx.x * 256 + t;
    int node = idx >> 4, q = idx & 15;
    if (node >= n) return;

    const float4* xw4 = (const float4*)xw;
    float4 acc = __ldg(&((const float4*)bias)[q]);
    float s = dinv[node]; s *= s;
    float4 self = __ldg(&xw4[(size_t)node * 16 + q]);
    acc.x = fmaf(s, self.x, acc.x);
    acc.y = fmaf(s, self.y, acc.y);
    acc.z = fmaf(s, self.z, acc.z);
    acc.w = fmaf(s, self.w, acc.w);

    int p  = start[node];
    int p1 = p + cnt[node];
    // unroll-4: batch all loads before FMAs to maximize loads in flight
    for (; p + 4 <= p1; p += 4) {
        int2 a0 = __ldg(&adj[p]);
        int2 a1 = __ldg(&adj[p + 1]);
        int2 a2 = __ldg(&adj[p + 2]);
        int2 a3 = __ldg(&adj[p + 3]);
        float4 v0 = __ldg(&xw4[(size_t)a0.x * 16 + q]);
        float4 v1 = __ldg(&xw4[(size_t)a1.x * 16 + q]);
        float4 v2 = __ldg(&xw4[(size_t)a2.x * 16 + q]);
        float4 v3 = __ldg(&xw4[(size_t)a3.x * 16 + q]);
        float w0 = __int_as_float(a0.y), w1 = __int_as_float(a1.y);
        float w2 = __int_as_float(a2.y), w3 = __int_as_float(a3.y);
        acc.x = fmaf(w3, v3.x, fmaf(w2, v2.x, fmaf(w1, v1.x, fmaf(w0, v0.x, acc.x))));
        acc.y = fmaf(w3, v3.y, fmaf(w2, v2.y, fmaf(w1, v1.y, fmaf(w0, v0.y, acc.y))));
        acc.z = fmaf(w3, v3.z, fmaf(w2, v2.z, fmaf(w1, v1.z, fmaf(w0, v0.z, acc.z))));
        acc.w = fmaf(w3, v3.w, fmaf(w2, v2.w, fmaf(w1, v1.w, fmaf(w0, v0.w, acc.w))));
    }
    for (; p < p1; p++) {
        int2 a = __ldg(&adj[p]);
        float w = __int_as_float(a.y);
        float4 v = __ldg(&xw4[(size_t)a.x * 16 + q]);
        acc.x = fmaf(w, v.x, acc.x);
        acc.y = fmaf(w, v.y, acc.y);
        acc.z = fmaf(w, v.z, acc.z);
        acc.w = fmaf(w, v.w, acc.w);
    }
    ((float4*)agg)[(size_t)node * 16 + q] = acc;
}

// ---------------- BN stats: column sums / sumsq ----------------
__global__ void bn_stats_kernel(const float* __restrict__ agg, int n) {
    int t = threadIdx.x;              // 256
    int col = t & 63, sub = t >> 6;   // 4 sub-rows
    float s = 0.f, s2 = 0.f;
    for (int i = blockIdx.x * 4 + sub; i < n; i += gridDim.x * 4) {
        float v = agg[(size_t)i * HD + col];
        s += v;
        s2 = fmaf(v, v, s2);
    }
    __shared__ float sh0[256], sh1[256];
    sh0[t] = s; sh1[t] = s2;
    __syncthreads();
    if (sub == 0) {
        double ds  = (double)sh0[t] + sh0[t + 64] + sh0[t + 128] + sh0[t + 192];
        double ds2 = (double)sh1[t] + sh1[t + 64] + sh1[t + 128] + sh1[t + 192];
        atomicAdd(&g_sum[col], ds);
        atomicAdd(&g_sumsq[col], ds2);
    }
}

__global__ void bn_finalize_kernel(const float* __restrict__ g, const float* __restrict__ be, int n) {
    int t = threadIdx.x;
    if (t >= HD) return;
    double mean = g_sum[t] / n;
    double var  = g_sumsq[t] / n - mean * mean;
    float a = g[t] * rsqrtf((float)var + BN_EPS);
    g_a[t] = a;
    g_c[t] = be[t] - (float)mean * a;
}

// ---------------- fused BN+ReLU+GEMM: xw = relu(bn(agg)) @ W ----------------
// block = 128 threads = 64 nodes, 2 threads per node (32 outputs each).
__global__ void __launch_bounds__(128)
xw_fused_kernel(const float* __restrict__ in, const float* __restrict__ W,
                float* __restrict__ out, int n) {
    __shared__ float tile[64 * TS];
    __shared__ float Ws[HD * HD];
    __shared__ float as[HD], cs[HD];
    int t = threadIdx.x;
    for (int i = t; i < HD * HD; i += 128) Ws[i] = W[i];
    if (t < HD) { as[t] = g_a[t]; cs[t] = g_c[t]; }

    int base = blockIdx.x * 64;
    int nv = min(64, n - base);
    const float4* in4 = (const float4*)(in + (size_t)base * HD);
    for (int i = t; i < nv * 16; i += 128) {
        float4 v = __ldg(&in4[i]);
        float* p = &tile[(i >> 4) * TS + (i & 15) * 4];
        p[0] = v.x; p[1] = v.y; p[2] = v.z; p[3] = v.w;
    }
    __syncthreads();

    int node = t >> 1, h = t & 1;
    bool act = (base + node) < n;
    float acc[32];
    #pragma unroll
    for (int j = 0; j < 32; j++) acc[j] = 0.f;
    if (act) {
        const float* row = &tile[node * TS];
        const float* wb  = &Ws[h * 32];
        #pragma unroll 4
        for (int k = 0; k < HD; k++) {
            float v = fmaxf(fmaf(row[k], as[k], cs[k]), 0.f);
            #pragma unroll
            for (int j = 0; j < 32; j++) acc[j] = fmaf(v, wb[k * HD + j], acc[j]);
        }
    }
    __syncthreads();
    if (act) {
        float* dst = &tile[node * TS + h * 32];
        #pragma unroll
        for (int j = 0; j < 32; j++) dst[j] = acc[j];
    }
    __syncthreads();
    float4* out4 = (float4*)(out + (size_t)base * HD);
    for (int i = t; i < nv * 16; i += 128) {
        float* p = &tile[(i >> 4) * TS + (i & 15) * 4];
        out4[i] = make_float4(p[0], p[1], p[2], p[3]);
    }
}

// ---------------- final FC: out = relu(bn(agg)) @ wfc + bfc ----------------
__global__ void __launch_bounds__(128)
fc_kernel(const float* __restrict__ agg, const float* __restrict__ wfc,
          const float* __restrict__ bfc, float* __restrict__ out, int n) {
    __shared__ float tile[128 * TS];
    __shared__ float Wf[HD * OUTD];
    __shared__ float as[HD], cs[HD];
    int t = threadIdx.x;
    if (t < HD) { as[t] = g_a[t]; cs[t] = g_c[t]; }
    if (t < HD) ((float4*)Wf)[t] = ((const float4*)wfc)[t];

    int base = blockIdx.x * 128;
    int nv = min(128, n - base);
    const float4* in4 = (const float4*)(agg + (size_t)base * HD);
    for (int i = t; i < nv * 16; i += 128) {
        float4 v = __ldg(&in4[i]);
        float* p = &tile[(i >> 4) * TS + (i & 15) * 4];
        p[0] = v.x; p[1] = v.y; p[2] = v.z; p[3] = v.w;
    }
    __syncthreads();
    if (t < nv) {
        float a0 = __ldg(&bfc[0]), a1 = __ldg(&bfc[1]);
        float a2 = __ldg(&bfc[2]), a3 = __ldg(&bfc[3]);
        const float* row = &tile[t * TS];
        #pragma unroll 8
        for (int k = 0; k < HD; k++) {
            float v = fmaxf(fmaf(row[k], as[k], cs[k]), 0.f);
            a0 = fmaf(v, Wf[k * 4 + 0], a0);
            a1 = fmaf(v, Wf[k * 4 + 1], a1);
            a2 = fmaf(v, Wf[k * 4 + 2], a2);
            a3 = fmaf(v, Wf[k * 4 + 3], a3);
        }
        ((float4*)out)[base + t] = make_float4(a0, a1, a2, a3);
    }
}

// ---------------- host orchestration ----------------
extern "C" void kernel_launch(void* const* d_in, const int* in_sizes, int n_in,
                              void* d_out, int out_size) {
    const float* x   = (const float*)d_in[0];
    const int*   sei = (const int*)d_in[1];
    const int*   tei = (const int*)d_in[2];
    const float* w1  = (const float*)d_in[3];
    const float* b1  = (const float*)d_in[4];
    const float* g1  = (const float*)d_in[5];
    const float* be1 = (const float*)d_in[6];
    const float* w2  = (const float*)d_in[7];
    const float* b2  = (const float*)d_in[8];
    const float* g2  = (const float*)d_in[9];
    const float* be2 = (const float*)d_in[10];
    const float* w3  = (const float*)d_in[11];
    const float* b3  = (const float*)d_in[12];
    const float* g3  = (const float*)d_in[13];
    const float* be3 = (const float*)d_in[14];
    const float* w4  = (const float*)d_in[15];
    const float* b4  = (const float*)d_in[16];
    const float* g4  = (const float*)d_in[17];
    const float* be4 = (const float*)d_in[18];
    const float* wfc = (const float*)d_in[19];
    const float* bfc = (const float*)d_in[20];
    float* out = (float*)d_out;

    const int n = in_sizes[0] / IND;   // 100000
    const int e = in_sizes[1] / 2;     // 1600000
    const int* s_rows = sei;  const int* s_cols = sei + e;
    const int* t_rows = tei;  const int* t_cols = tei + e;

    int *cnt_s, *cnt_t, *start_s, *start_t, *cur_s, *cur_t, *bsum;
    float *dv_s, *dv_t, *xw, *agg;
    int2 *adj_s, *adj_t;
    cudaGetSymbolAddress((void**)&cnt_s, g_cnt_s);
    cudaGetSymbolAddress((void**)&cnt_t, g_cnt_t);
    cudaGetSymbolAddress((void**)&start_s, g_start_s);
    cudaGetSymbolAddress((void**)&start_t, g_start_t);
    cudaGetSymbolAddress((void**)&cur_s, g_cur_s);
    cudaGetSymbolAddress((void**)&cur_t, g_cur_t);
    cudaGetSymbolAddress((void**)&dv_s, g_dv_s);
    cudaGetSymbolAddress((void**)&dv_t, g_dv_t);
    cudaGetSymbolAddress((void**)&xw, g_xw);
    cudaGetSymbolAddress((void**)&agg, g_agg);
    cudaGetSymbolAddress((void**)&adj_s, g_adj_s);
    cudaGetSymbolAddress((void**)&adj_t, g_adj_t);
    cudaGetSymbolAddress((void**)&bsum, g_bsum);

    const int eg = cdiv(e, 256);
    const int ng16 = cdiv((long long)n * 16, 256);

    // ---- CSR build (once per graph, reused by 2 layers each) ----
    zero_cnt_kernel<<<cdiv(n, 256), 256>>>(cnt_s, cnt_t, n);
    count_kernel<<<eg, 256>>>(s_cols, t_cols, cnt_s, cnt_t, e);
    dinv_kernel<<<cdiv(n, 256), 256>>>(cnt_s, cnt_t, dv_s, dv_t, n);
    scan1_kernel<<<dim3(SCAN_NBLK, 2), 1024>>>(cnt_s, start_s, cnt_t, start_t, bsum, n);
    scan2_kernel<<<2, 128>>>(bsum);
    scan3_kernel<<<dim3(cdiv(n, 256), 2), 256>>>(start_s, cur_s, start_t, cur_t, bsum, n);
    place_kernel<<<eg, 256>>>(s_rows, s_cols, t_rows, t_cols, dv_s, dv_t,
                              cur_s, cur_t, adj_s, adj_t, e);

    // ---- layer 1 (spatial) ----
    xw1_kernel<<<ng16, 256>>>(x, w1, xw, n);
    gather_kernel<<<ng16, 256>>>(adj_s, start_s, cnt_s, dv_s, xw, b1, agg, n);
    bn_stats_kernel<<<512, 256>>>(agg, n);
    bn_finalize_kernel<<<1, 64>>>(g1, be1, n);

    // ---- layer 2 (spatial) ----
    xw_fused_kernel<<<cdiv(n, 64), 128>>>(agg, w2, xw, n);
    gather_kernel<<<ng16, 256>>>(adj_s, start_s, cnt_s, dv_s, xw, b2, agg, n);
    bn_stats_kernel<<<512, 256>>>(agg, n);
    bn_finalize_kernel<<<1, 64>>>(g2, be2, n);

    // ---- layer 3 (temporal) ----
    xw_fused_kernel<<<cdiv(n, 64), 128>>>(agg, w3, xw, n);
    gather_kernel<<<ng16, 256>>>(adj_t, start_t, cnt_t, dv_t, xw, b3, agg, n);
    bn_stats_kernel<<<512, 256>>>(agg, n);
    bn_finalize_kernel<<<1, 64>>>(g3, be3, n);

    // ---- layer 4 (temporal) ----
    xw_fused_kernel<<<cdiv(n, 64), 128>>>(agg, w4, xw, n);
    gather_kernel<<<ng16, 256>>>(adj_t, start_t, cnt_t, dv_t, xw, b4, agg, n);
    bn_stats_kernel<<<512, 256>>>(agg, n);
    bn_finalize_kernel<<<1, 64>>>(g4, be4, n);

    // ---- final FC ----
    fc_kernel<<<cdiv(n, 128), 128>>>(agg, wfc, bfc, out, n);
}